// round 1
// baseline (speedup 1.0000x reference)
#include <cuda_runtime.h>

// InteractionArch: B x (1 dense + 26 sparse) x 128 -> strict upper triangle of
// per-row Gram matrix (27x27 -> 351 entries).
//
// Strategy: one warp per batch row. Load the 27x128 combined matrix into
// shared memory (padded stride 136 to limit bank conflicts). 28 lanes each
// own a 4x4 tile of the upper-triangular 7x7 tile grid of the 27x27 (padded
// to 28x28) Gram matrix, accumulating full K=128 dot products in registers
// via float4 loads. Results staged through smem for coalesced global writes.

#define FEAT 27
#define DIM 128
#define NPAIR 351          // 27*26/2
#define SROW 136           // padded row stride in floats (16B-aligned, conflict-limited)
#define ROWS 28            // pad to 28 rows (row 27 zero) so 4x4 tiles never OOB
#define BPB 3              // batches (warps) per block
#define THREADS (BPB * 32)

__global__ __launch_bounds__(THREADS)
void interaction_kernel(const float* __restrict__ dense,
                        const float* __restrict__ sparse,
                        float* __restrict__ out,
                        int B)
{
    __shared__ float sA[BPB][ROWS * SROW];

    const int warp = threadIdx.x >> 5;
    const int lane = threadIdx.x & 31;
    const int b = blockIdx.x * BPB + warp;
    if (b >= B) return;

    float* A = sA[warp];

    // ---- Load phase: 27 rows x 128 floats, float4 per lane per row ----
    const int col = lane * 4;
    {
        float4 v = *reinterpret_cast<const float4*>(dense + (size_t)b * DIM + col);
        *reinterpret_cast<float4*>(A + 0 * SROW + col) = v;
    }
    const float* sp = sparse + (size_t)b * 26 * DIM;
#pragma unroll
    for (int r = 1; r <= 26; ++r) {
        float4 v = *reinterpret_cast<const float4*>(sp + (size_t)(r - 1) * DIM + col);
        *reinterpret_cast<float4*>(A + r * SROW + col) = v;
    }
    // zero pad row 27
    *reinterpret_cast<float4*>(A + 27 * SROW + col) = make_float4(0.f, 0.f, 0.f, 0.f);
    __syncwarp();

    // ---- Tile mapping: 28 upper-triangular 4x4 tiles of the 7x7 tile grid ----
    int ti = 0, tj = 0;
    {
        int rem = lane;
        int t = 0;
        while (t < 7 && rem >= 7 - t) { rem -= 7 - t; ++t; }
        ti = t;
        tj = t + rem;   // lanes 28..31 get garbage; they are masked below
    }
    const bool active = (lane < 28);
    const int i0 = ti * 4;
    const int j0 = tj * 4;

    float acc[4][4] = {};

    if (active) {
        const float* Ai = A + i0 * SROW;
        const float* Aj = A + j0 * SROW;
#pragma unroll 2
        for (int k = 0; k < DIM; k += 4) {
            float4 a0 = *reinterpret_cast<const float4*>(Ai + 0 * SROW + k);
            float4 a1 = *reinterpret_cast<const float4*>(Ai + 1 * SROW + k);
            float4 a2 = *reinterpret_cast<const float4*>(Ai + 2 * SROW + k);
            float4 a3 = *reinterpret_cast<const float4*>(Ai + 3 * SROW + k);
            float4 c0 = *reinterpret_cast<const float4*>(Aj + 0 * SROW + k);
            float4 c1 = *reinterpret_cast<const float4*>(Aj + 1 * SROW + k);
            float4 c2 = *reinterpret_cast<const float4*>(Aj + 2 * SROW + k);
            float4 c3 = *reinterpret_cast<const float4*>(Aj + 3 * SROW + k);

            float4 av[4] = {a0, a1, a2, a3};
            float4 cv[4] = {c0, c1, c2, c3};
#pragma unroll
            for (int x = 0; x < 4; ++x) {
#pragma unroll
                for (int y = 0; y < 4; ++y) {
                    acc[x][y] += av[x].x * cv[y].x;
                    acc[x][y] += av[x].y * cv[y].y;
                    acc[x][y] += av[x].z * cv[y].z;
                    acc[x][y] += av[x].w * cv[y].w;
                }
            }
        }
    }

    __syncwarp();   // everyone done reading A before we overwrite it as staging

    if (active) {
#pragma unroll
        for (int x = 0; x < 4; ++x) {
#pragma unroll
            for (int y = 0; y < 4; ++y) {
                int i = i0 + x;
                int j = j0 + y;
                if (i < j && j < FEAT) {
                    // row-major strict-upper-triangle index
                    int idx = i * (2 * FEAT - i - 1) / 2 + (j - i - 1);
                    A[idx] = acc[x][y];
                }
            }
        }
    }

    __syncwarp();

    // ---- Coalesced writeout ----
    float* ob = out + (size_t)b * NPAIR;
    for (int idx = lane; idx < NPAIR; idx += 32) {
        ob[idx] = A[idx];
    }
}

extern "C" void kernel_launch(void* const* d_in, const int* in_sizes, int n_in,
                              void* d_out, int out_size)
{
    const float* dense  = (const float*)d_in[0];   // (B, 128)
    const float* sparse = (const float*)d_in[1];   // (B, 26, 128)
    float* out = (float*)d_out;                    // (B, 351)

    const int B = in_sizes[0] / DIM;
    const int grid = (B + BPB - 1) / BPB;
    interaction_kernel<<<grid, THREADS>>>(dense, sparse, out, B);
}

// round 2
// speedup vs baseline: 2.7277x; 2.7277x over previous
#include <cuda_runtime.h>

// InteractionArch: B x (1 dense + 26 sparse) x 128 -> strict upper triangle of
// per-row Gram matrix (27x27 -> 351 entries).
//
// One warp per batch row. 27x128 combined matrix lives in smem with a
// conflict-free float4 swizzle: chunk (r, c) stored at chunk position
// ((c + r + (r>>3)) & 31) within row r. The (r>>3) term makes the bank group
// (pos mod 8) depend on bits of r above bit 2, so the 7 distinct tile rows
// touched by a quarter-warp phase land in 7 distinct bank groups.
// 28 lanes each own a 4x4 tile of the 7x7 tile grid of the padded 28x28 Gram.
// Accumulation uses packed fma.rn.f32x2 (FFMA2) -> half the FMA instructions.

#define FEAT 27
#define DIM 128
#define NPAIR 351          // 27*26/2
#define ROWS 28            // pad to 28 rows (row 27 zero)
#define BPB 3              // batches (warps) per block
#define THREADS (BPB * 32)

__device__ __forceinline__ void fma2(unsigned long long& d,
                                     unsigned long long a,
                                     unsigned long long b) {
    asm("fma.rn.f32x2 %0, %1, %2, %0;" : "+l"(d) : "l"(a), "l"(b));
}

__device__ __forceinline__ float hsum2(unsigned long long p) {
    unsigned int lo, hi;
    asm("mov.b64 {%0, %1}, %2;" : "=r"(lo), "=r"(hi) : "l"(p));
    return __uint_as_float(lo) + __uint_as_float(hi);
}

// swizzled float offset of float4-chunk c within row r
__device__ __forceinline__ int swz(int r, int c) {
    return r * DIM + (((c + r + (r >> 3)) & 31) << 2);
}

__global__ __launch_bounds__(THREADS)
void interaction_kernel(const float* __restrict__ dense,
                        const float* __restrict__ sparse,
                        float* __restrict__ out,
                        int B)
{
    __shared__ float sA[BPB][ROWS * DIM];   // 3 * 14336 B = 43008 B

    const int warp = threadIdx.x >> 5;
    const int lane = threadIdx.x & 31;
    const int b = blockIdx.x * BPB + warp;
    if (b >= B) return;

    float* A = sA[warp];

    // ---- Load phase: each lane stores chunk c=lane of every row (swizzled).
    // Within one row, positions (lane + s_r) & 31 form a permutation -> conflict-free.
    {
        float4 v = *reinterpret_cast<const float4*>(dense + (size_t)b * DIM + lane * 4);
        *reinterpret_cast<float4*>(A + swz(0, lane)) = v;
    }
    const float* sp = sparse + (size_t)b * 26 * DIM;
#pragma unroll
    for (int r = 1; r <= 26; ++r) {
        float4 v = *reinterpret_cast<const float4*>(sp + (size_t)(r - 1) * DIM + lane * 4);
        *reinterpret_cast<float4*>(A + swz(r, lane)) = v;
    }
    *reinterpret_cast<float4*>(A + swz(27, lane)) = make_float4(0.f, 0.f, 0.f, 0.f);
    __syncwarp();

    // ---- Tile mapping: lane -> (ti, tj), 28 upper-triangular 4x4 tiles of 7x7 grid
    int ti = 0, tj = 0;
    {
        int rem = lane;
        int t = 0;
        while (t < 7 && rem >= 7 - t) { rem -= 7 - t; ++t; }
        ti = t;
        tj = t + rem;
    }
    const bool active = (lane < 28);
    const int i0 = ti * 4;
    const int j0 = tj * 4;

    unsigned long long acc[4][4] = {};   // each is a packed f32x2 partial pair-sum

    if (active) {
        // per-row swizzle salt and base offsets
        int sa[4], sc[4], ba[4], bc[4];
#pragma unroll
        for (int x = 0; x < 4; ++x) {
            int ra = i0 + x, rc = j0 + x;
            sa[x] = ra + (ra >> 3);  ba[x] = ra * DIM;
            sc[x] = rc + (rc >> 3);  bc[x] = rc * DIM;
        }

#pragma unroll 4
        for (int c = 0; c < 32; ++c) {
            unsigned long long av[4][2], cv[4][2];
#pragma unroll
            for (int x = 0; x < 4; ++x) {
                ulonglong2 t0 = *reinterpret_cast<const ulonglong2*>(
                    A + ba[x] + (((c + sa[x]) & 31) << 2));
                av[x][0] = t0.x; av[x][1] = t0.y;
                ulonglong2 t1 = *reinterpret_cast<const ulonglong2*>(
                    A + bc[x] + (((c + sc[x]) & 31) << 2));
                cv[x][0] = t1.x; cv[x][1] = t1.y;
            }
#pragma unroll
            for (int x = 0; x < 4; ++x)
#pragma unroll
                for (int y = 0; y < 4; ++y) {
                    fma2(acc[x][y], av[x][0], cv[y][0]);
                    fma2(acc[x][y], av[x][1], cv[y][1]);
                }
        }
    }

    __syncwarp();   // all lanes done reading A before staging overwrites it

    if (active) {
#pragma unroll
        for (int x = 0; x < 4; ++x)
#pragma unroll
            for (int y = 0; y < 4; ++y) {
                int i = i0 + x;
                int j = j0 + y;
                if (i < j && j < FEAT) {
                    int idx = i * (2 * FEAT - i - 1) / 2 + (j - i - 1);
                    A[idx] = hsum2(acc[x][y]);
                }
            }
    }

    __syncwarp();

    // ---- Coalesced writeout ----
    float* ob = out + (size_t)b * NPAIR;
#pragma unroll
    for (int it = 0; it < 11; ++it) {
        int idx = it * 32 + lane;
        if (idx < NPAIR) ob[idx] = A[idx];
    }
}

extern "C" void kernel_launch(void* const* d_in, const int* in_sizes, int n_in,
                              void* d_out, int out_size)
{
    const float* dense  = (const float*)d_in[0];   // (B, 128)
    const float* sparse = (const float*)d_in[1];   // (B, 26, 128)
    float* out = (float*)d_out;                    // (B, 351)

    const int B = in_sizes[0] / DIM;
    const int grid = (B + BPB - 1) / BPB;
    interaction_kernel<<<grid, THREADS>>>(dense, sparse, out, B);
}

// round 3
// speedup vs baseline: 2.7905x; 1.0230x over previous
#include <cuda_runtime.h>

// InteractionArch: B x (1 dense + 26 sparse) x 128 -> strict upper triangle of
// per-row Gram matrix (27x27 -> 351 entries).
//
// One warp (= one block) handles THREE batch rows. Each batch row's 28x128
// (27 real + 1 zero pad) matrix lives in smem. The 27x27 Gram triangle is
// covered by the 10 upper tiles of a 4x4 grid of 7x7 tiles; 3 rows x 10 tiles
// = 30 lanes (lanes 30,31 mirror lane 29 and are write-masked).
//
// Swizzle: float4-chunk c of row r in buffer w sits at chunk position
// (c + 3r + w) & 31. Within every octet phase of every tile-row load
// instruction the touched bank-groups (pos mod 8) are pairwise distinct
// (3*7 = 21 = 5 mod 8 generates {0,5,2,7}; +w separates buffers), so all
// LDS.128 run at the 4-cycle conflict-free floor.
//
// Accumulation uses packed fma.rn.f32x2 (98 FFMA2 + 14 LDS.128 per k-chunk:
// 3.5 products per shared-load vs 2.0 for 4x4 tiles).

#define FEAT 27
#define DIM 128
#define NPAIR 351           // 27*26/2
#define ROWS 28             // padded rows per batch (row 27 zero)
#define BUFF (ROWS * DIM)   // 3584 floats per batch row
#define RPW 3               // batch rows per warp

__device__ __forceinline__ void fma2(unsigned long long& d,
                                     unsigned long long a,
                                     unsigned long long b) {
    asm("fma.rn.f32x2 %0, %1, %2, %0;" : "+l"(d) : "l"(a), "l"(b));
}

__device__ __forceinline__ float hsum2(unsigned long long p) {
    unsigned int lo, hi;
    asm("mov.b64 {%0, %1}, %2;" : "=r"(lo), "=r"(hi) : "l"(p));
    return __uint_as_float(lo) + __uint_as_float(hi);
}

__global__ __launch_bounds__(32)
void interaction_kernel(const float* __restrict__ dense,
                        const float* __restrict__ sparse,
                        float* __restrict__ out,
                        int B)
{
    __shared__ float A[RPW * BUFF];   // 43008 bytes

    const int lane = threadIdx.x;     // blockDim = 32
    const long bbase = (long)blockIdx.x * RPW;

    // ---- Load phase: lane owns chunk c = lane of every row, every buffer ----
#pragma unroll
    for (int w = 0; w < RPW; ++w) {
        const long b = bbase + w;
        if (b < B) {
            float* buf = A + w * BUFF;
            {
                float4 v = *reinterpret_cast<const float4*>(dense + b * DIM + lane * 4);
                *reinterpret_cast<float4*>(buf + (((lane + w) & 31) << 2)) = v;
            }
            const float* sp = sparse + b * 26 * DIM;
#pragma unroll
            for (int r = 1; r <= 26; ++r) {
                float4 v = *reinterpret_cast<const float4*>(sp + (size_t)(r - 1) * DIM + lane * 4);
                *reinterpret_cast<float4*>(buf + r * DIM + (((lane + 3 * r + w) & 31) << 2)) = v;
            }
            *reinterpret_cast<float4*>(buf + 27 * DIM + (((lane + 81 + w) & 31) << 2)) =
                make_float4(0.f, 0.f, 0.f, 0.f);
        }
    }
    __syncwarp();

    // ---- Lane -> (buffer w, tile t) ; tiles: (0,0)(0,1)(0,2)(0,3)(1,1)(1,2)(1,3)(2,2)(2,3)(3,3)
    const int lw = (lane < 30) ? lane : 29;
    const int w  = lw / 10;
    const int t  = lw % 10;
    const int ti = (t >= 4) + (t >= 7) + (t >= 9);
    const int start = 4 * ti - ((ti * (ti - 1)) >> 1);
    const int tj = ti + (t - start);

    const int i0 = 7 * ti;
    const int j0 = 7 * tj;

    // precomputed per-row base offsets and swizzle salts
    int ab[7], cb[7], as[7], cs[7];
#pragma unroll
    for (int x = 0; x < 7; ++x) {
        const int ra = i0 + x, rc = j0 + x;
        ab[x] = w * BUFF + ra * DIM;  as[x] = 3 * ra + w;
        cb[x] = w * BUFF + rc * DIM;  cs[x] = 3 * rc + w;
    }

    unsigned long long acc[49] = {};  // acc[x*7+y], each a packed f32x2

#pragma unroll 4
    for (int c = 0; c < 32; ++c) {
        ulonglong2 av[7];
#pragma unroll
        for (int x = 0; x < 7; ++x)
            av[x] = *reinterpret_cast<const ulonglong2*>(A + ab[x] + (((c + as[x]) & 31) << 2));
#pragma unroll
        for (int y = 0; y < 7; ++y) {
            ulonglong2 cv = *reinterpret_cast<const ulonglong2*>(A + cb[y] + (((c + cs[y]) & 31) << 2));
#pragma unroll
            for (int x = 0; x < 7; ++x) {
                fma2(acc[x * 7 + y], av[x].x, cv.x);
                fma2(acc[x * 7 + y], av[x].y, cv.y);
            }
        }
    }

    __syncwarp();   // all lanes done reading A before staging overwrites it

    // ---- Stage results into smem (buffer w reused as staging) ----
    const bool wvalid = (lane < 30) && (bbase + w < B);
    if (wvalid) {
        float* stg = A + w * BUFF;
#pragma unroll
        for (int x = 0; x < 7; ++x) {
#pragma unroll
            for (int y = 0; y < 7; ++y) {
                const int i = i0 + x;
                const int j = j0 + y;
                if (i < j && j < FEAT) {
                    const int idx = i * (2 * FEAT - i - 1) / 2 + (j - i - 1);
                    stg[idx] = hsum2(acc[x * 7 + y]);
                }
            }
        }
    }
    __syncwarp();

    // ---- Coalesced writeout ----
#pragma unroll
    for (int ww = 0; ww < RPW; ++ww) {
        const long b = bbase + ww;
        if (b < B) {
            const float* stg = A + ww * BUFF;
            float* ob = out + b * NPAIR;
#pragma unroll
            for (int it = 0; it < 11; ++it) {
                const int idx = it * 32 + lane;
                if (idx < NPAIR) ob[idx] = stg[idx];
            }
        }
    }
}

extern "C" void kernel_launch(void* const* d_in, const int* in_sizes, int n_in,
                              void* d_out, int out_size)
{
    const float* dense  = (const float*)d_in[0];   // (B, 128)
    const float* sparse = (const float*)d_in[1];   // (B, 26, 128)
    float* out = (float*)d_out;                    // (B, 351)

    const int B = in_sizes[0] / DIM;
    const int grid = (B + RPW - 1) / RPW;
    interaction_kernel<<<grid, 32>>>(dense, sparse, out, B);
}